// round 3
// baseline (speedup 1.0000x reference)
#include <cuda_runtime.h>
#include <cuda_bf16.h>
#include <cstdint>

#define DEVINL __device__ __forceinline__

static constexpr int B = 4096;
static constexpr int D = 1024;
static constexpr int BM = 128;        // CTA M tile
static constexpr int BN = 256;        // CTA N tile
static constexpr int BK = 64;         // K chunk (64 bf16 = 128 B rows, SW128)
static constexpr int NT = B / BN;     // 16 N tiles
static constexpr int MT = B / BM;     // 32 M tiles
static constexpr int KC = D / BK;     // 16 K chunks
static constexpr int STAGES = 3;
static constexpr float SCORE_SCALE = 20.0f;

static constexpr int A_SZ = BM * BK * 2;        // 16384
static constexpr int B_SZ = BN * BK * 2;        // 32768
static constexpr int STAGE_SZ = A_SZ + B_SZ;    // 49152
static constexpr int SMEM_BYTES = STAGES * STAGE_SZ + 1024;

// Scratch (allocation-free: __device__ globals)
__device__ __nv_bfloat16 g_an[B * D];      // normalized anchors, bf16
__device__ __nv_bfloat16 g_pn[B * D];      // normalized pos_negs, bf16
__device__ float2 g_part[B * NT];          // per-(row, ntile) (max, sumexp)
__device__ float g_diag[B];                // diag scores

DEVINL uint32_t smem_u32(const void* p) {
    uint32_t a;
    asm("{ .reg .u64 t; cvta.to.shared.u64 t, %1; cvt.u32.u64 %0, t; }"
        : "=r"(a) : "l"(p));
    return a;
}

DEVINL uint32_t swz128(uint32_t o) { return o ^ ((o >> 3) & 0x70); }

DEVINL void cp_async16(uint32_t dst, const void* src) {
    asm volatile("cp.async.cg.shared.global [%0], [%1], 16;"
                 :: "r"(dst), "l"(src) : "memory");
}

DEVINL void cp_commit() { asm volatile("cp.async.commit_group;" ::: "memory"); }

template <int N>
DEVINL void cp_wait() { asm volatile("cp.async.wait_group %0;" :: "n"(N) : "memory"); }

DEVINL void ldsm_x4(uint32_t addr, uint32_t& r0, uint32_t& r1, uint32_t& r2, uint32_t& r3) {
    asm volatile("ldmatrix.sync.aligned.m8n8.x4.shared.b16 {%0,%1,%2,%3}, [%4];"
                 : "=r"(r0), "=r"(r1), "=r"(r2), "=r"(r3) : "r"(addr));
}

DEVINL void mma_bf16(float* c, const uint32_t* a, uint32_t b0, uint32_t b1) {
    asm volatile(
        "mma.sync.aligned.m16n8k16.row.col.f32.bf16.bf16.f32 "
        "{%0,%1,%2,%3}, {%4,%5,%6,%7}, {%8,%9}, {%0,%1,%2,%3};"
        : "+f"(c[0]), "+f"(c[1]), "+f"(c[2]), "+f"(c[3])
        : "r"(a[0]), "r"(a[1]), "r"(a[2]), "r"(a[3]), "r"(b0), "r"(b1));
}

// ============================================================
// Kernel 1: L2-normalize rows, write bf16 (warp-per-row, MLP=8)
// ============================================================
__global__ void __launch_bounds__(256) k_norm(const float* __restrict__ a,
                                              const float* __restrict__ p) {
    int w = threadIdx.x >> 5, lane = threadIdx.x & 31;
    int row = blockIdx.x * 8 + w;
    const float* src = (row < B) ? (a + (size_t)row * D) : (p + (size_t)(row - B) * D);
    __nv_bfloat16* dst = (row < B) ? (g_an + (size_t)row * D) : (g_pn + (size_t)(row - B) * D);

    float4 v[8];
#pragma unroll
    for (int r = 0; r < 8; ++r)
        v[r] = reinterpret_cast<const float4*>(src)[r * 32 + lane];

    float ss = 0.f;
#pragma unroll
    for (int r = 0; r < 8; ++r)
        ss += v[r].x * v[r].x + v[r].y * v[r].y + v[r].z * v[r].z + v[r].w * v[r].w;
#pragma unroll
    for (int o = 16; o > 0; o >>= 1) ss += __shfl_xor_sync(0xffffffffu, ss, o);

    float inv = 1.0f / fmaxf(sqrtf(ss), 1e-8f);

#pragma unroll
    for (int r = 0; r < 8; ++r) {
        __nv_bfloat162 o0 = __floats2bfloat162_rn(v[r].x * inv, v[r].y * inv);
        __nv_bfloat162 o1 = __floats2bfloat162_rn(v[r].z * inv, v[r].w * inv);
        uint2 pk = make_uint2(*reinterpret_cast<uint32_t*>(&o0),
                              *reinterpret_cast<uint32_t*>(&o1));
        reinterpret_cast<uint2*>(dst)[r * 32 + lane] = pk;
    }
}

// ============================================================
// Kernel 2: bf16 mma.sync GEMM (128x256 tile, 64x64 warp tile)
//           + fused partial LSE
// ============================================================
__global__ void __launch_bounds__(256, 1) k_gemm_lse() {
    extern __shared__ char smem_raw[];
    uint32_t sb0 = smem_u32(smem_raw);
    uint32_t sb = (sb0 + 1023u) & ~1023u;
    char* base = smem_raw + (sb - sb0);

    const int tid = threadIdx.x;
    const int lane = tid & 31;
    const int w = tid >> 5;            // 0..7
    const int wm = w >> 2;             // 0..1  (M warp, 64 rows)
    const int wn = w & 3;              // 0..3  (N warp, 64 cols)
    const int bx = blockIdx.x;         // N tile (0..15)
    const int by = blockIdx.y;         // M tile (0..31)

    const __nv_bfloat16* Ag = g_an + (size_t)(by * BM) * D;
    const __nv_bfloat16* Bg = g_pn + (size_t)(bx * BN) * D;

    auto issue = [&](int kc, int s) {
        uint32_t sa = sb + s * STAGE_SZ;
        uint32_t sbB = sa + A_SZ;
#pragma unroll
        for (int i = 0; i < 4; ++i) {
            int idx = i * 256 + tid;        // 0..1023 (A: 128 rows x 8 chunks)
            int r = idx >> 3, c = idx & 7;
            cp_async16(sa + swz128((uint32_t)(r * 128 + c * 16)),
                       Ag + (size_t)r * D + kc * BK + c * 8);
        }
#pragma unroll
        for (int i = 0; i < 8; ++i) {
            int idx = i * 256 + tid;        // 0..2047 (B: 256 rows x 8 chunks)
            int r = idx >> 3, c = idx & 7;
            cp_async16(sbB + swz128((uint32_t)(r * 128 + c * 16)),
                       Bg + (size_t)r * D + kc * BK + c * 8);
        }
        cp_commit();
    };

    float acc[4][8][4];
#pragma unroll
    for (int ri = 0; ri < 4; ++ri)
#pragma unroll
        for (int nf = 0; nf < 8; ++nf)
#pragma unroll
            for (int c = 0; c < 4; ++c) acc[ri][nf][c] = 0.f;

    issue(0, 0);
    issue(1, 1);

    const int a_row_in = (lane & 7) + ((lane >> 3) & 1) * 8;
    const int a_kb_in  = (lane >> 4) * 16;
    const int b_n_in   = (lane & 7) + ((lane >> 4) ? 8 : 0);
    const int b_kb_in  = ((lane >> 3) & 1) * 16;

    for (int kc = 0; kc < KC; ++kc) {
        cp_wait<STAGES - 2>();
        __syncthreads();
        if (kc + 2 < KC) issue(kc + 2, (kc + 2) % STAGES);

        uint32_t sA = sb + (kc % STAGES) * STAGE_SZ;
        uint32_t sB = sA + A_SZ;

#pragma unroll
        for (int s16 = 0; s16 < 4; ++s16) {
            int kb = s16 * 32;
            uint32_t a[4][4];
#pragma unroll
            for (int ri = 0; ri < 4; ++ri) {
                int row = wm * 64 + ri * 16 + a_row_in;
                ldsm_x4(sA + swz128((uint32_t)(row * 128 + kb + a_kb_in)),
                        a[ri][0], a[ri][1], a[ri][2], a[ri][3]);
            }
            uint32_t bf[4][4];
#pragma unroll
            for (int p = 0; p < 4; ++p) {
                int n = wn * 64 + p * 16 + b_n_in;
                ldsm_x4(sB + swz128((uint32_t)(n * 128 + kb + b_kb_in)),
                        bf[p][0], bf[p][1], bf[p][2], bf[p][3]);
            }
#pragma unroll
            for (int ri = 0; ri < 4; ++ri)
#pragma unroll
                for (int nf = 0; nf < 8; ++nf)
                    mma_bf16(acc[ri][nf], a[ri],
                             bf[nf >> 1][(nf & 1) * 2], bf[nf >> 1][(nf & 1) * 2 + 1]);
        }
        __syncthreads();
    }

    // ---- Epilogue: fused partial logsumexp + diag ----
    const int g = lane >> 2, tg = lane & 3;
    float2* hm = reinterpret_cast<float2*>(base);   // 128 rows x 4 N-quarters

#pragma unroll
    for (int ri = 0; ri < 4; ++ri) {
#pragma unroll
        for (int h = 0; h < 2; ++h) {
            int rowl = wm * 64 + ri * 16 + h * 8 + g;
            int rowg = by * BM + rowl;
            float v[16];
            float mx = -1e30f;
#pragma unroll
            for (int nf = 0; nf < 8; ++nf) {
#pragma unroll
                for (int c = 0; c < 2; ++c) {
                    float val = SCORE_SCALE * acc[ri][nf][h * 2 + c];
                    v[nf * 2 + c] = val;
                    mx = fmaxf(mx, val);
                    int col = bx * BN + wn * 64 + nf * 8 + tg * 2 + c;
                    if (col == rowg) g_diag[rowg] = val;
                }
            }
            mx = fmaxf(mx, __shfl_xor_sync(0xffffffffu, mx, 1));
            mx = fmaxf(mx, __shfl_xor_sync(0xffffffffu, mx, 2));
            float sm = 0.f;
#pragma unroll
            for (int i = 0; i < 16; ++i) sm += __expf(v[i] - mx);
            sm += __shfl_xor_sync(0xffffffffu, sm, 1);
            sm += __shfl_xor_sync(0xffffffffu, sm, 2);
            if (tg == 0) hm[rowl * 4 + wn] = make_float2(mx, sm);
        }
    }
    __syncthreads();
    if (tid < 128) {
        float M = -1e30f;
        float2 q[4];
#pragma unroll
        for (int i = 0; i < 4; ++i) {
            q[i] = hm[tid * 4 + i];
            M = fmaxf(M, q[i].x);
        }
        float S = 0.f;
#pragma unroll
        for (int i = 0; i < 4; ++i) S += q[i].y * __expf(q[i].x - M);
        g_part[(size_t)(by * BM + tid) * NT + bx] = make_float2(M, S);
    }
}

// ============================================================
// Kernel 3: merge partials -> mean(logZ - diag)
// ============================================================
__global__ void __launch_bounds__(512) k_reduce(float* __restrict__ out) {
    __shared__ float red[512];
    int tid = threadIdx.x;
    float acc = 0.f;
    for (int row = tid; row < B; row += 512) {
        float M = -1e30f;
        float2 p[NT];
#pragma unroll
        for (int i = 0; i < NT; ++i) {
            p[i] = g_part[(size_t)row * NT + i];
            M = fmaxf(M, p[i].x);
        }
        float S = 0.f;
#pragma unroll
        for (int i = 0; i < NT; ++i) S += p[i].y * expf(p[i].x - M);
        float logZ = M + logf(S);
        acc += logZ - g_diag[row];
    }
    red[tid] = acc;
    __syncthreads();
#pragma unroll
    for (int s = 256; s > 0; s >>= 1) {
        if (tid < s) red[tid] += red[tid + s];
        __syncthreads();
    }
    if (tid == 0) out[0] = red[0] / (float)B;
}

// ============================================================
extern "C" void kernel_launch(void* const* d_in, const int* in_sizes, int n_in,
                              void* d_out, int out_size) {
    const float* anchor = (const float*)d_in[0];
    const float* pnegs  = (const float*)d_in[1];
    float* out = (float*)d_out;

    cudaFuncSetAttribute(k_gemm_lse, cudaFuncAttributeMaxDynamicSharedMemorySize,
                         SMEM_BYTES);

    k_norm<<<1024, 256>>>(anchor, pnegs);
    k_gemm_lse<<<dim3(NT, MT), 256, SMEM_BYTES>>>();
    k_reduce<<<1, 512>>>(out);
}

// round 4
// speedup vs baseline: 1.3040x; 1.3040x over previous
#include <cuda_runtime.h>
#include <cuda_bf16.h>
#include <cuda_fp8.h>
#include <cstdint>

#define DEVINL __device__ __forceinline__

static constexpr int B = 4096;
static constexpr int D = 1024;
static constexpr int BM = 128;        // CTA M tile
static constexpr int BN = 128;        // CTA N tile
static constexpr int BK = 128;        // K chunk (128 fp8 = 128 B rows, SW128)
static constexpr int NT = B / BN;     // 32 N tiles
static constexpr int MT = B / BM;     // 32 M tiles
static constexpr int KC = D / BK;     // 8 K chunks
static constexpr int STAGES = 3;
static constexpr float FP8_SCALE = 32.0f;           // stored = 32 * x_hat
static constexpr float SCORE_MUL = 20.0f / (FP8_SCALE * FP8_SCALE);

static constexpr int A_SZ = BM * BK;            // 16384 bytes
static constexpr int B_SZ = BN * BK;            // 16384 bytes
static constexpr int STAGE_SZ = A_SZ + B_SZ;    // 32768
static constexpr int SMEM_BYTES = STAGES * STAGE_SZ + 1024;

// Scratch (allocation-free: __device__ globals)
__device__ uint8_t g_an[B * D];            // normalized anchors, e4m3 (x32)
__device__ uint8_t g_pn[B * D];            // normalized pos_negs, e4m3 (x32)
__device__ float2 g_part[B * NT];          // per-(row, ntile) (max, sumexp)
__device__ float g_diag[B];                // diag scores

DEVINL uint32_t smem_u32(const void* p) {
    uint32_t a;
    asm("{ .reg .u64 t; cvta.to.shared.u64 t, %1; cvt.u32.u64 %0, t; }"
        : "=r"(a) : "l"(p));
    return a;
}

DEVINL uint32_t swz128(uint32_t o) { return o ^ ((o >> 3) & 0x70); }

DEVINL void cp_async16(uint32_t dst, const void* src) {
    asm volatile("cp.async.cg.shared.global [%0], [%1], 16;"
                 :: "r"(dst), "l"(src) : "memory");
}

DEVINL void cp_commit() { asm volatile("cp.async.commit_group;" ::: "memory"); }

template <int N>
DEVINL void cp_wait() { asm volatile("cp.async.wait_group %0;" :: "n"(N) : "memory"); }

DEVINL void ldsm_x4(uint32_t addr, uint32_t& r0, uint32_t& r1, uint32_t& r2, uint32_t& r3) {
    asm volatile("ldmatrix.sync.aligned.m8n8.x4.shared.b16 {%0,%1,%2,%3}, [%4];"
                 : "=r"(r0), "=r"(r1), "=r"(r2), "=r"(r3) : "r"(addr));
}

DEVINL void mma_fp8(float* c, const uint32_t* a, uint32_t b0, uint32_t b1) {
    asm volatile(
        "mma.sync.aligned.m16n8k32.row.col.f32.e4m3.e4m3.f32 "
        "{%0,%1,%2,%3}, {%4,%5,%6,%7}, {%8,%9}, {%0,%1,%2,%3};"
        : "+f"(c[0]), "+f"(c[1]), "+f"(c[2]), "+f"(c[3])
        : "r"(a[0]), "r"(a[1]), "r"(a[2]), "r"(a[3]), "r"(b0), "r"(b1));
}

// ============================================================
// Kernel 1: L2-normalize rows, write e4m3 (scaled by 32)
// ============================================================
__global__ void __launch_bounds__(256) k_norm(const float* __restrict__ a,
                                              const float* __restrict__ p) {
    int w = threadIdx.x >> 5, lane = threadIdx.x & 31;
    int row = blockIdx.x * 8 + w;
    const float* src = (row < B) ? (a + (size_t)row * D) : (p + (size_t)(row - B) * D);
    uint8_t* dst = (row < B) ? (g_an + (size_t)row * D) : (g_pn + (size_t)(row - B) * D);

    float4 v[8];
#pragma unroll
    for (int r = 0; r < 8; ++r)
        v[r] = reinterpret_cast<const float4*>(src)[r * 32 + lane];

    float ss = 0.f;
#pragma unroll
    for (int r = 0; r < 8; ++r)
        ss += v[r].x * v[r].x + v[r].y * v[r].y + v[r].z * v[r].z + v[r].w * v[r].w;
#pragma unroll
    for (int o = 16; o > 0; o >>= 1) ss += __shfl_xor_sync(0xffffffffu, ss, o);

    float inv = FP8_SCALE / fmaxf(sqrtf(ss), 1e-8f);

#pragma unroll
    for (int r = 0; r < 8; ++r) {
        __nv_fp8x2_storage_t lo = __nv_cvt_float2_to_fp8x2(
            make_float2(v[r].x * inv, v[r].y * inv), __NV_SATFINITE, __NV_E4M3);
        __nv_fp8x2_storage_t hi = __nv_cvt_float2_to_fp8x2(
            make_float2(v[r].z * inv, v[r].w * inv), __NV_SATFINITE, __NV_E4M3);
        uint32_t pk = (uint32_t)lo | ((uint32_t)hi << 16);
        reinterpret_cast<uint32_t*>(dst)[r * 32 + lane] = pk;
    }
}

// ============================================================
// Kernel 2: e4m3 mma.sync GEMM (128x128 tile, 32x64 warp tile)
//           + fused partial LSE
// ============================================================
__global__ void __launch_bounds__(256, 2) k_gemm_lse() {
    extern __shared__ char smem_raw[];
    uint32_t sb0 = smem_u32(smem_raw);
    uint32_t sb = (sb0 + 1023u) & ~1023u;
    char* base = smem_raw + (sb - sb0);

    const int tid = threadIdx.x;
    const int lane = tid & 31;
    const int w = tid >> 5;            // 0..7
    const int wm = w >> 1;             // 0..3  (M warp, 32 rows)
    const int wn = w & 1;              // 0..1  (N warp, 64 cols)
    const int bx = blockIdx.x;         // N tile
    const int by = blockIdx.y;         // M tile

    const uint8_t* Ag = g_an + (size_t)(by * BM) * D;
    const uint8_t* Bg = g_pn + (size_t)(bx * BN) * D;

    // One K chunk = 128 rows x 128 bytes for A and B each
    auto issue = [&](int kc, int s) {
        uint32_t sa = sb + s * STAGE_SZ;
        uint32_t sbB = sa + A_SZ;
#pragma unroll
        for (int i = 0; i < 4; ++i) {
            int idx = i * 256 + tid;        // 0..1023 (128 rows x 8 x 16B)
            int r = idx >> 3, c = idx & 7;
            cp_async16(sa + swz128((uint32_t)(r * 128 + c * 16)),
                       Ag + (size_t)r * D + kc * BK + c * 16);
        }
#pragma unroll
        for (int i = 0; i < 4; ++i) {
            int idx = i * 256 + tid;
            int r = idx >> 3, c = idx & 7;
            cp_async16(sbB + swz128((uint32_t)(r * 128 + c * 16)),
                       Bg + (size_t)r * D + kc * BK + c * 16);
        }
        cp_commit();
    };

    float acc[2][8][4];
#pragma unroll
    for (int ri = 0; ri < 2; ++ri)
#pragma unroll
        for (int nf = 0; nf < 8; ++nf)
#pragma unroll
            for (int c = 0; c < 4; ++c) acc[ri][nf][c] = 0.f;

    issue(0, 0);
    issue(1, 1);

    // ldmatrix lane addressing (b16-view of fp8 k32 fragments)
    const int a_row_in = (lane & 7) + ((lane >> 3) & 1) * 8;  // 0..15
    const int a_kb_in  = (lane >> 4) * 16;                    // 0 or 16 bytes
    const int b_n_in   = (lane & 7) + ((lane >> 4) ? 8 : 0);  // 0..15
    const int b_kb_in  = ((lane >> 3) & 1) * 16;              // 0 or 16 bytes

    for (int kc = 0; kc < KC; ++kc) {
        cp_wait<STAGES - 2>();
        __syncthreads();
        if (kc + 2 < KC) issue(kc + 2, (kc + 2) % STAGES);

        uint32_t sA = sb + (kc % STAGES) * STAGE_SZ;
        uint32_t sB = sA + A_SZ;

#pragma unroll
        for (int s32 = 0; s32 < 4; ++s32) {
            int kb = s32 * 32;  // 32 bytes = k32 fp8 per step
            uint32_t a[2][4];
#pragma unroll
            for (int ri = 0; ri < 2; ++ri) {
                int row = wm * 32 + ri * 16 + a_row_in;
                ldsm_x4(sA + swz128((uint32_t)(row * 128 + kb + a_kb_in)),
                        a[ri][0], a[ri][1], a[ri][2], a[ri][3]);
            }
            uint32_t bf[4][4];
#pragma unroll
            for (int p = 0; p < 4; ++p) {
                int n = wn * 64 + p * 16 + b_n_in;
                ldsm_x4(sB + swz128((uint32_t)(n * 128 + kb + b_kb_in)),
                        bf[p][0], bf[p][1], bf[p][2], bf[p][3]);
            }
#pragma unroll
            for (int ri = 0; ri < 2; ++ri)
#pragma unroll
                for (int nf = 0; nf < 8; ++nf)
                    mma_fp8(acc[ri][nf], a[ri],
                            bf[nf >> 1][(nf & 1) * 2], bf[nf >> 1][(nf & 1) * 2 + 1]);
        }
        __syncthreads();
    }

    // ---- Epilogue: fused partial logsumexp + diag ----
    const int g = lane >> 2, tg = lane & 3;
    float2* hm = reinterpret_cast<float2*>(base);   // 128 rows x 2 halves

#pragma unroll
    for (int ri = 0; ri < 2; ++ri) {
#pragma unroll
        for (int h = 0; h < 2; ++h) {
            int rowl = wm * 32 + ri * 16 + h * 8 + g;
            int rowg = by * BM + rowl;
            float v[16];
            float mx = -1e30f;
#pragma unroll
            for (int nf = 0; nf < 8; ++nf) {
#pragma unroll
                for (int c = 0; c < 2; ++c) {
                    float val = SCORE_MUL * acc[ri][nf][h * 2 + c];
                    v[nf * 2 + c] = val;
                    mx = fmaxf(mx, val);
                    int col = bx * BN + wn * 64 + nf * 8 + tg * 2 + c;
                    if (col == rowg) g_diag[rowg] = val;
                }
            }
            mx = fmaxf(mx, __shfl_xor_sync(0xffffffffu, mx, 1));
            mx = fmaxf(mx, __shfl_xor_sync(0xffffffffu, mx, 2));
            float sm = 0.f;
#pragma unroll
            for (int i = 0; i < 16; ++i) sm += __expf(v[i] - mx);
            sm += __shfl_xor_sync(0xffffffffu, sm, 1);
            sm += __shfl_xor_sync(0xffffffffu, sm, 2);
            if (tg == 0) hm[rowl * 2 + wn] = make_float2(mx, sm);
        }
    }
    __syncthreads();
    if (tid < 128) {
        float2 a0 = hm[tid * 2 + 0];
        float2 a1 = hm[tid * 2 + 1];
        float M = fmaxf(a0.x, a1.x);
        float S = a0.y * __expf(a0.x - M) + a1.y * __expf(a1.x - M);
        g_part[(size_t)(by * BM + tid) * NT + bx] = make_float2(M, S);
    }
}

// ============================================================
// Kernel 3: merge partials -> mean(logZ - diag)
// ============================================================
__global__ void __launch_bounds__(512) k_reduce(float* __restrict__ out) {
    __shared__ float red[512];
    int tid = threadIdx.x;
    float acc = 0.f;
    for (int row = tid; row < B; row += 512) {
        float M = -1e30f;
        float2 p[NT];
#pragma unroll
        for (int i = 0; i < NT; ++i) {
            p[i] = g_part[(size_t)row * NT + i];
            M = fmaxf(M, p[i].x);
        }
        float S = 0.f;
#pragma unroll
        for (int i = 0; i < NT; ++i) S += p[i].y * expf(p[i].x - M);
        float logZ = M + logf(S);
        acc += logZ - g_diag[row];
    }
    red[tid] = acc;
    __syncthreads();
#pragma unroll
    for (int s = 256; s > 0; s >>= 1) {
        if (tid < s) red[tid] += red[tid + s];
        __syncthreads();
    }
    if (tid == 0) out[0] = red[0] / (float)B;
}

// ============================================================
extern "C" void kernel_launch(void* const* d_in, const int* in_sizes, int n_in,
                              void* d_out, int out_size) {
    const float* anchor = (const float*)d_in[0];
    const float* pnegs  = (const float*)d_in[1];
    float* out = (float*)d_out;

    cudaFuncSetAttribute(k_gemm_lse, cudaFuncAttributeMaxDynamicSharedMemorySize,
                         SMEM_BYTES);

    k_norm<<<1024, 256>>>(anchor, pnegs);
    k_gemm_lse<<<dim3(NT, MT), 256, SMEM_BYTES>>>();
    k_reduce<<<1, 512>>>(out);
}

// round 5
// speedup vs baseline: 2.1430x; 1.6435x over previous
#include <cuda_runtime.h>
#include <cuda_bf16.h>
#include <cuda_fp16.h>
#include <cuda_fp8.h>
#include <cstdint>

#define DEVINL __device__ __forceinline__

static constexpr int B = 4096;
static constexpr int D = 1024;
static constexpr int BM = 128;        // CTA M tile
static constexpr int BN = 128;        // CTA N tile
static constexpr int BK = 128;        // K chunk (128 fp8 = 128 B rows, SW128)
static constexpr int NT = B / BN;     // 32 N tiles
static constexpr int MT = B / BM;     // 32 M tiles
static constexpr int KC = D / BK;     // 8 K chunks
static constexpr int STAGES = 3;
static constexpr float FP8_SCALE = 32.0f;           // stored = 32 * x_hat
static constexpr float SCORE_MUL = 20.0f / (FP8_SCALE * FP8_SCALE);

static constexpr int A_SZ = BM * BK;            // 16384 bytes
static constexpr int B_SZ = BN * BK;            // 16384 bytes
static constexpr int STAGE_SZ = A_SZ + B_SZ;    // 32768
static constexpr int SMEM_BYTES = STAGES * STAGE_SZ + 1024;

// Scratch (allocation-free: __device__ globals)
__device__ uint8_t g_an[B * D];            // normalized anchors, e4m3 (x32)
__device__ uint8_t g_pn[B * D];            // normalized pos_negs, e4m3 (x32)
__device__ float2 g_part[B * NT];          // per-(row, ntile) (max, sumexp)
__device__ float g_diag[B];                // diag scores

DEVINL uint32_t smem_u32(const void* p) {
    uint32_t a;
    asm("{ .reg .u64 t; cvta.to.shared.u64 t, %1; cvt.u32.u64 %0, t; }"
        : "=r"(a) : "l"(p));
    return a;
}

DEVINL uint32_t swz128(uint32_t o) { return o ^ ((o >> 3) & 0x70); }

DEVINL void cp_async16(uint32_t dst, const void* src) {
    asm volatile("cp.async.cg.shared.global [%0], [%1], 16;"
                 :: "r"(dst), "l"(src) : "memory");
}

DEVINL void cp_commit() { asm volatile("cp.async.commit_group;" ::: "memory"); }

template <int N>
DEVINL void cp_wait() { asm volatile("cp.async.wait_group %0;" :: "n"(N) : "memory"); }

DEVINL void ldsm_x4(uint32_t addr, uint32_t& r0, uint32_t& r1, uint32_t& r2, uint32_t& r3) {
    asm volatile("ldmatrix.sync.aligned.m8n8.x4.shared.b16 {%0,%1,%2,%3}, [%4];"
                 : "=r"(r0), "=r"(r1), "=r"(r2), "=r"(r3) : "r"(addr));
}

// fp8 e4m3 MMA with f16 accumulator (2 D-regs instead of 4)
DEVINL void mma_fp8_h(uint32_t* c, const uint32_t* a, uint32_t b0, uint32_t b1) {
    asm volatile(
        "mma.sync.aligned.m16n8k32.row.col.f16.e4m3.e4m3.f16 "
        "{%0,%1}, {%2,%3,%4,%5}, {%6,%7}, {%0,%1};"
        : "+r"(c[0]), "+r"(c[1])
        : "r"(a[0]), "r"(a[1]), "r"(a[2]), "r"(a[3]), "r"(b0), "r"(b1));
}

// ============================================================
// Kernel 1: L2-normalize rows, write e4m3 (scaled by 32)
// ============================================================
__global__ void __launch_bounds__(256) k_norm(const float* __restrict__ a,
                                              const float* __restrict__ p) {
    int w = threadIdx.x >> 5, lane = threadIdx.x & 31;
    int row = blockIdx.x * 8 + w;
    const float* src = (row < B) ? (a + (size_t)row * D) : (p + (size_t)(row - B) * D);
    uint8_t* dst = (row < B) ? (g_an + (size_t)row * D) : (g_pn + (size_t)(row - B) * D);

    float4 v[8];
#pragma unroll
    for (int r = 0; r < 8; ++r)
        v[r] = reinterpret_cast<const float4*>(src)[r * 32 + lane];

    float ss = 0.f;
#pragma unroll
    for (int r = 0; r < 8; ++r)
        ss += v[r].x * v[r].x + v[r].y * v[r].y + v[r].z * v[r].z + v[r].w * v[r].w;
#pragma unroll
    for (int o = 16; o > 0; o >>= 1) ss += __shfl_xor_sync(0xffffffffu, ss, o);

    float inv = FP8_SCALE / fmaxf(sqrtf(ss), 1e-8f);

#pragma unroll
    for (int r = 0; r < 8; ++r) {
        __nv_fp8x2_storage_t lo = __nv_cvt_float2_to_fp8x2(
            make_float2(v[r].x * inv, v[r].y * inv), __NV_SATFINITE, __NV_E4M3);
        __nv_fp8x2_storage_t hi = __nv_cvt_float2_to_fp8x2(
            make_float2(v[r].z * inv, v[r].w * inv), __NV_SATFINITE, __NV_E4M3);
        uint32_t pk = (uint32_t)lo | ((uint32_t)hi << 16);
        reinterpret_cast<uint32_t*>(dst)[r * 32 + lane] = pk;
    }
}

// ============================================================
// Kernel 2: e4m3 mma.sync f16-accum GEMM (128x128 tile, 32x64 warp)
//           + fused partial LSE
// ============================================================
__global__ void __launch_bounds__(256, 2) k_gemm_lse() {
    extern __shared__ char smem_raw[];
    uint32_t sb0 = smem_u32(smem_raw);
    uint32_t sb = (sb0 + 1023u) & ~1023u;
    char* base = smem_raw + (sb - sb0);

    const int tid = threadIdx.x;
    const int lane = tid & 31;
    const int w = tid >> 5;            // 0..7
    const int wm = w >> 1;             // 0..3  (M warp, 32 rows)
    const int wn = w & 1;              // 0..1  (N warp, 64 cols)
    const int bx = blockIdx.x;         // N tile
    const int by = blockIdx.y;         // M tile

    const uint8_t* Ag = g_an + (size_t)(by * BM) * D;
    const uint8_t* Bg = g_pn + (size_t)(bx * BN) * D;

    auto issue = [&](int kc, int s) {
        uint32_t sa = sb + s * STAGE_SZ;
        uint32_t sbB = sa + A_SZ;
#pragma unroll
        for (int i = 0; i < 4; ++i) {
            int idx = i * 256 + tid;        // 0..1023 (128 rows x 8 x 16B)
            int r = idx >> 3, c = idx & 7;
            cp_async16(sa + swz128((uint32_t)(r * 128 + c * 16)),
                       Ag + (size_t)r * D + kc * BK + c * 16);
        }
#pragma unroll
        for (int i = 0; i < 4; ++i) {
            int idx = i * 256 + tid;
            int r = idx >> 3, c = idx & 7;
            cp_async16(sbB + swz128((uint32_t)(r * 128 + c * 16)),
                       Bg + (size_t)r * D + kc * BK + c * 16);
        }
        cp_commit();
    };

    // f16x2 accumulators: [ri][nf][2]  (reg0 = rows g, reg1 = rows g+8)
    uint32_t acc[2][8][2];
#pragma unroll
    for (int ri = 0; ri < 2; ++ri)
#pragma unroll
        for (int nf = 0; nf < 8; ++nf) {
            acc[ri][nf][0] = 0u;
            acc[ri][nf][1] = 0u;
        }

    issue(0, 0);
    issue(1, 1);

    const int a_row_in = (lane & 7) + ((lane >> 3) & 1) * 8;  // 0..15
    const int a_kb_in  = (lane >> 4) * 16;                    // 0 or 16 bytes
    const int b_n_in   = (lane & 7) + ((lane >> 4) ? 8 : 0);  // 0..15
    const int b_kb_in  = ((lane >> 3) & 1) * 16;              // 0 or 16 bytes

    for (int kc = 0; kc < KC; ++kc) {
        cp_wait<STAGES - 2>();
        __syncthreads();
        if (kc + 2 < KC) issue(kc + 2, (kc + 2) % STAGES);

        uint32_t sA = sb + (kc % STAGES) * STAGE_SZ;
        uint32_t sB = sA + A_SZ;

#pragma unroll
        for (int s32 = 0; s32 < 4; ++s32) {
            int kb = s32 * 32;  // 32 bytes = k32 fp8 per step
            uint32_t a[2][4];
#pragma unroll
            for (int ri = 0; ri < 2; ++ri) {
                int row = wm * 32 + ri * 16 + a_row_in;
                ldsm_x4(sA + swz128((uint32_t)(row * 128 + kb + a_kb_in)),
                        a[ri][0], a[ri][1], a[ri][2], a[ri][3]);
            }
            uint32_t bf[4][4];
#pragma unroll
            for (int p = 0; p < 4; ++p) {
                int n = wn * 64 + p * 16 + b_n_in;
                ldsm_x4(sB + swz128((uint32_t)(n * 128 + kb + b_kb_in)),
                        bf[p][0], bf[p][1], bf[p][2], bf[p][3]);
            }
#pragma unroll
            for (int ri = 0; ri < 2; ++ri)
#pragma unroll
                for (int nf = 0; nf < 8; ++nf)
                    mma_fp8_h(acc[ri][nf], a[ri],
                              bf[nf >> 1][(nf & 1) * 2], bf[nf >> 1][(nf & 1) * 2 + 1]);
        }
        __syncthreads();
    }

    // ---- Epilogue: fused partial logsumexp + diag ----
    const int g = lane >> 2, tg = lane & 3;
    float2* hm = reinterpret_cast<float2*>(base);   // 128 rows x 2 halves

#pragma unroll
    for (int ri = 0; ri < 2; ++ri) {
#pragma unroll
        for (int h = 0; h < 2; ++h) {
            int rowl = wm * 32 + ri * 16 + h * 8 + g;
            int rowg = by * BM + rowl;
            float v[16];
            float mx = -1e30f;
#pragma unroll
            for (int nf = 0; nf < 8; ++nf) {
                float2 pr = __half22float2(
                    *reinterpret_cast<const __half2*>(&acc[ri][nf][h]));
#pragma unroll
                for (int c = 0; c < 2; ++c) {
                    float val = SCORE_MUL * ((c == 0) ? pr.x : pr.y);
                    v[nf * 2 + c] = val;
                    mx = fmaxf(mx, val);
                    int col = bx * BN + wn * 64 + nf * 8 + tg * 2 + c;
                    if (col == rowg) g_diag[rowg] = val;
                }
            }
            mx = fmaxf(mx, __shfl_xor_sync(0xffffffffu, mx, 1));
            mx = fmaxf(mx, __shfl_xor_sync(0xffffffffu, mx, 2));
            float sm = 0.f;
#pragma unroll
            for (int i = 0; i < 16; ++i) sm += __expf(v[i] - mx);
            sm += __shfl_xor_sync(0xffffffffu, sm, 1);
            sm += __shfl_xor_sync(0xffffffffu, sm, 2);
            if (tg == 0) hm[rowl * 2 + wn] = make_float2(mx, sm);
        }
    }
    __syncthreads();
    if (tid < 128) {
        float2 a0 = hm[tid * 2 + 0];
        float2 a1 = hm[tid * 2 + 1];
        float M = fmaxf(a0.x, a1.x);
        float S = a0.y * __expf(a0.x - M) + a1.y * __expf(a1.x - M);
        g_part[(size_t)(by * BM + tid) * NT + bx] = make_float2(M, S);
    }
}

// ============================================================
// Kernel 3a: zero the output scalar
// ============================================================
__global__ void k_zero(float* __restrict__ out) { out[0] = 0.f; }

// ============================================================
// Kernel 3b: merge partials -> mean(logZ - diag), 16 CTAs + atomicAdd
// ============================================================
__global__ void __launch_bounds__(256) k_reduce(float* __restrict__ out) {
    __shared__ float red[256];
    int tid = threadIdx.x;
    int row = blockIdx.x * 256 + tid;

    float M = -1e30f;
    float2 p[NT];
#pragma unroll
    for (int i = 0; i < NT; ++i) {
        p[i] = g_part[(size_t)row * NT + i];
        M = fmaxf(M, p[i].x);
    }
    float S = 0.f;
#pragma unroll
    for (int i = 0; i < NT; ++i) S += p[i].y * expf(p[i].x - M);
    float acc = (M + logf(S)) - g_diag[row];

    red[tid] = acc;
    __syncthreads();
#pragma unroll
    for (int s = 128; s > 0; s >>= 1) {
        if (tid < s) red[tid] += red[tid + s];
        __syncthreads();
    }
    if (tid == 0) atomicAdd(out, red[0] * (1.0f / (float)B));
}

// ============================================================
extern "C" void kernel_launch(void* const* d_in, const int* in_sizes, int n_in,
                              void* d_out, int out_size) {
    const float* anchor = (const float*)d_in[0];
    const float* pnegs  = (const float*)d_in[1];
    float* out = (float*)d_out;

    cudaFuncSetAttribute(k_gemm_lse, cudaFuncAttributeMaxDynamicSharedMemorySize,
                         SMEM_BYTES);

    k_norm<<<1024, 256>>>(anchor, pnegs);
    k_zero<<<1, 1>>>(out);
    k_gemm_lse<<<dim3(NT, MT), 256, SMEM_BYTES>>>();
    k_reduce<<<16, 256>>>(out);
}

// round 7
// speedup vs baseline: 2.1853x; 1.0197x over previous
#include <cuda_runtime.h>
#include <cuda_bf16.h>
#include <cuda_fp16.h>
#include <cuda_fp8.h>
#include <cstdint>

#define DEVINL __device__ __forceinline__

static constexpr int B = 4096;
static constexpr int D = 1024;
static constexpr int BM = 128;        // CTA M tile
static constexpr int BN = 128;        // CTA N tile
static constexpr int BK = 128;        // K chunk (128 fp8 = 128 B rows, SW128)
static constexpr int NT = B / BN;     // 32 N tiles
static constexpr int MT = B / BM;     // 32 M tiles
static constexpr int KC = D / BK;     // 8 K chunks
static constexpr int STAGES = 3;
static constexpr float FP8_SCALE = 32.0f;           // stored = 32 * x_hat
static constexpr float SCORE_MUL = 20.0f / (FP8_SCALE * FP8_SCALE);

static constexpr int A_SZ = BM * BK;            // 16384 bytes
static constexpr int B_SZ = BN * BK;            // 16384 bytes
static constexpr int STAGE_SZ = A_SZ + B_SZ;    // 32768
static constexpr int SMEM_BYTES = STAGES * STAGE_SZ + 1024;

// Scratch (allocation-free: __device__ globals)
__device__ uint8_t g_an[B * D];            // normalized anchors, e4m3 (x32)
__device__ uint8_t g_pn[B * D];            // normalized pos_negs, e4m3 (x32)
__device__ float2 g_part[NT * B];          // [ntile][row] (max, sumexp) - transposed!
__device__ float g_diag[B];                // diag scores

DEVINL uint32_t smem_u32(const void* p) {
    uint32_t a;
    asm("{ .reg .u64 t; cvta.to.shared.u64 t, %1; cvt.u32.u64 %0, t; }"
        : "=r"(a) : "l"(p));
    return a;
}

DEVINL uint32_t swz128(uint32_t o) { return o ^ ((o >> 3) & 0x70); }

DEVINL void cp_async16(uint32_t dst, const void* src) {
    asm volatile("cp.async.cg.shared.global [%0], [%1], 16;"
                 :: "r"(dst), "l"(src) : "memory");
}

DEVINL void cp_commit() { asm volatile("cp.async.commit_group;" ::: "memory"); }

template <int N>
DEVINL void cp_wait() { asm volatile("cp.async.wait_group %0;" :: "n"(N) : "memory"); }

DEVINL void ldsm_x4(uint32_t addr, uint32_t& r0, uint32_t& r1, uint32_t& r2, uint32_t& r3) {
    asm volatile("ldmatrix.sync.aligned.m8n8.x4.shared.b16 {%0,%1,%2,%3}, [%4];"
                 : "=r"(r0), "=r"(r1), "=r"(r2), "=r"(r3) : "r"(addr));
}

// fp8 e4m3 MMA with f16 accumulator (2 D-regs instead of 4)
DEVINL void mma_fp8_h(uint32_t* c, const uint32_t* a, uint32_t b0, uint32_t b1) {
    asm volatile(
        "mma.sync.aligned.m16n8k32.row.col.f16.e4m3.e4m3.f16 "
        "{%0,%1}, {%2,%3,%4,%5}, {%6,%7}, {%0,%1};"
        : "+r"(c[0]), "+r"(c[1])
        : "r"(a[0]), "r"(a[1]), "r"(a[2]), "r"(a[3]), "r"(b0), "r"(b1));
}

// ============================================================
// Kernel 1: L2-normalize rows, write e4m3 (scaled by 32)
//           Two-phase: low register pressure, 2nd read hits L2
// ============================================================
__global__ void __launch_bounds__(256) k_norm(const float* __restrict__ a,
                                              const float* __restrict__ p) {
    int w = threadIdx.x >> 5, lane = threadIdx.x & 31;
    int row = blockIdx.x * 8 + w;
    const float* src = (row < B) ? (a + (size_t)row * D) : (p + (size_t)(row - B) * D);
    uint8_t* dst = (row < B) ? (g_an + (size_t)row * D) : (g_pn + (size_t)(row - B) * D);

    // Phase 1: sum of squares (values not retained)
    float ss = 0.f;
#pragma unroll
    for (int r = 0; r < 8; ++r) {
        float4 v = reinterpret_cast<const float4*>(src)[r * 32 + lane];
        ss += v.x * v.x + v.y * v.y + v.z * v.z + v.w * v.w;
    }
#pragma unroll
    for (int o = 16; o > 0; o >>= 1) ss += __shfl_xor_sync(0xffffffffu, ss, o);

    float inv = FP8_SCALE / fmaxf(sqrtf(ss), 1e-8f);

    // Phase 2: reload (L2-resident) and emit fp8
#pragma unroll
    for (int r = 0; r < 8; ++r) {
        float4 v = reinterpret_cast<const float4*>(src)[r * 32 + lane];
        __nv_fp8x2_storage_t lo = __nv_cvt_float2_to_fp8x2(
            make_float2(v.x * inv, v.y * inv), __NV_SATFINITE, __NV_E4M3);
        __nv_fp8x2_storage_t hi = __nv_cvt_float2_to_fp8x2(
            make_float2(v.z * inv, v.w * inv), __NV_SATFINITE, __NV_E4M3);
        uint32_t pk = (uint32_t)lo | ((uint32_t)hi << 16);
        reinterpret_cast<uint32_t*>(dst)[r * 32 + lane] = pk;
    }
}

// ============================================================
// Kernel 2: e4m3 mma.sync f16-accum GEMM (128x128 tile, 32x64 warp)
//           + fused partial LSE
// ============================================================
__global__ void __launch_bounds__(256, 2) k_gemm_lse() {
    extern __shared__ char smem_raw[];
    uint32_t sb0 = smem_u32(smem_raw);
    uint32_t sb = (sb0 + 1023u) & ~1023u;
    char* base = smem_raw + (sb - sb0);

    const int tid = threadIdx.x;
    const int lane = tid & 31;
    const int w = tid >> 5;            // 0..7
    const int wm = w >> 1;             // 0..3  (M warp, 32 rows)
    const int wn = w & 1;              // 0..1  (N warp, 64 cols)
    const int bx = blockIdx.x;         // N tile
    const int by = blockIdx.y;         // M tile

    const uint8_t* Ag = g_an + (size_t)(by * BM) * D;
    const uint8_t* Bg = g_pn + (size_t)(bx * BN) * D;

    auto issue = [&](int kc, int s) {
        uint32_t sa = sb + s * STAGE_SZ;
        uint32_t sbB = sa + A_SZ;
#pragma unroll
        for (int i = 0; i < 4; ++i) {
            int idx = i * 256 + tid;        // 0..1023 (128 rows x 8 x 16B)
            int r = idx >> 3, c = idx & 7;
            cp_async16(sa + swz128((uint32_t)(r * 128 + c * 16)),
                       Ag + (size_t)r * D + kc * BK + c * 16);
        }
#pragma unroll
        for (int i = 0; i < 4; ++i) {
            int idx = i * 256 + tid;
            int r = idx >> 3, c = idx & 7;
            cp_async16(sbB + swz128((uint32_t)(r * 128 + c * 16)),
                       Bg + (size_t)r * D + kc * BK + c * 16);
        }
        cp_commit();
    };

    // f16x2 accumulators: [ri][nf][2]  (reg0 = rows g, reg1 = rows g+8)
    uint32_t acc[2][8][2];
#pragma unroll
    for (int ri = 0; ri < 2; ++ri)
#pragma unroll
        for (int nf = 0; nf < 8; ++nf) {
            acc[ri][nf][0] = 0u;
            acc[ri][nf][1] = 0u;
        }

    issue(0, 0);
    issue(1, 1);

    const int a_row_in = (lane & 7) + ((lane >> 3) & 1) * 8;  // 0..15
    const int a_kb_in  = (lane >> 4) * 16;                    // 0 or 16 bytes
    const int b_n_in   = (lane & 7) + ((lane >> 4) ? 8 : 0);  // 0..15
    const int b_kb_in  = ((lane >> 3) & 1) * 16;              // 0 or 16 bytes

    for (int kc = 0; kc < KC; ++kc) {
        cp_wait<STAGES - 2>();
        __syncthreads();
        if (kc + 2 < KC) issue(kc + 2, (kc + 2) % STAGES);

        uint32_t sA = sb + (kc % STAGES) * STAGE_SZ;
        uint32_t sB = sA + A_SZ;

#pragma unroll
        for (int s32 = 0; s32 < 4; ++s32) {
            int kb = s32 * 32;  // 32 bytes = k32 fp8 per step
            uint32_t a[2][4];
#pragma unroll
            for (int ri = 0; ri < 2; ++ri) {
                int row = wm * 32 + ri * 16 + a_row_in;
                ldsm_x4(sA + swz128((uint32_t)(row * 128 + kb + a_kb_in)),
                        a[ri][0], a[ri][1], a[ri][2], a[ri][3]);
            }
            uint32_t bf[4][4];
#pragma unroll
            for (int p = 0; p < 4; ++p) {
                int n = wn * 64 + p * 16 + b_n_in;
                ldsm_x4(sB + swz128((uint32_t)(n * 128 + kb + b_kb_in)),
                        bf[p][0], bf[p][1], bf[p][2], bf[p][3]);
            }
#pragma unroll
            for (int ri = 0; ri < 2; ++ri)
#pragma unroll
                for (int nf = 0; nf < 8; ++nf)
                    mma_fp8_h(acc[ri][nf], a[ri],
                              bf[nf >> 1][(nf & 1) * 2], bf[nf >> 1][(nf & 1) * 2 + 1]);
        }
        __syncthreads();
    }

    // ---- Epilogue: fused partial logsumexp + diag ----
    const int g = lane >> 2, tg = lane & 3;
    float2* hm = reinterpret_cast<float2*>(base);   // 128 rows x 2 halves

#pragma unroll
    for (int ri = 0; ri < 2; ++ri) {
#pragma unroll
        for (int h = 0; h < 2; ++h) {
            int rowl = wm * 32 + ri * 16 + h * 8 + g;
            int rowg = by * BM + rowl;
            float v[16];
            float mx = -1e30f;
#pragma unroll
            for (int nf = 0; nf < 8; ++nf) {
                float2 pr = __half22float2(
                    *reinterpret_cast<const __half2*>(&acc[ri][nf][h]));
#pragma unroll
                for (int c = 0; c < 2; ++c) {
                    float val = SCORE_MUL * ((c == 0) ? pr.x : pr.y);
                    v[nf * 2 + c] = val;
                    mx = fmaxf(mx, val);
                    int col = bx * BN + wn * 64 + nf * 8 + tg * 2 + c;
                    if (col == rowg) g_diag[rowg] = val;
                }
            }
            mx = fmaxf(mx, __shfl_xor_sync(0xffffffffu, mx, 1));
            mx = fmaxf(mx, __shfl_xor_sync(0xffffffffu, mx, 2));
            float sm = 0.f;
#pragma unroll
            for (int i = 0; i < 16; ++i) sm += __expf(v[i] - mx);
            sm += __shfl_xor_sync(0xffffffffu, sm, 1);
            sm += __shfl_xor_sync(0xffffffffu, sm, 2);
            if (tg == 0) hm[rowl * 2 + wn] = make_float2(mx, sm);
        }
    }
    __syncthreads();
    if (tid < 128) {
        float2 a0 = hm[tid * 2 + 0];
        float2 a1 = hm[tid * 2 + 1];
        float M = fmaxf(a0.x, a1.x);
        float S = a0.y * __expf(a0.x - M) + a1.y * __expf(a1.x - M);
        // transposed layout: coalesced write (consecutive tid -> consecutive row)
        g_part[(size_t)bx * B + by * BM + tid] = make_float2(M, S);
    }
}

// ============================================================
// Kernel 3a: zero the output scalar
// ============================================================
__global__ void k_zero(float* __restrict__ out) { out[0] = 0.f; }

// ============================================================
// Kernel 3b: merge partials -> mean(logZ - diag)
//            32 CTAs x 128 threads, fully coalesced reads
// ============================================================
__global__ void __launch_bounds__(128) k_reduce(float* __restrict__ out) {
    __shared__ float red[128];
    int tid = threadIdx.x;
    int row = blockIdx.x * 128 + tid;

    float M = -1e30f;
    float2 p[NT];
#pragma unroll
    for (int i = 0; i < NT; ++i) {
        p[i] = g_part[(size_t)i * B + row];   // coalesced across warp
        M = fmaxf(M, p[i].x);
    }
    float S = 0.f;
#pragma unroll
    for (int i = 0; i < NT; ++i) S += p[i].y * expf(p[i].x - M);
    float acc = (M + logf(S)) - g_diag[row];

    red[tid] = acc;
    __syncthreads();
#pragma unroll
    for (int s = 64; s > 0; s >>= 1) {
        if (tid < s) red[tid] += red[tid + s];
        __syncthreads();
    }
    if (tid == 0) atomicAdd(out, red[0] * (1.0f / (float)B));
}

// ============================================================
extern "C" void kernel_launch(void* const* d_in, const int* in_sizes, int n_in,
                              void* d_out, int out_size) {
    const float* anchor = (const float*)d_in[0];
    const float* pnegs  = (const float*)d_in[1];
    float* out = (float*)d_out;

    cudaFuncSetAttribute(k_gemm_lse, cudaFuncAttributeMaxDynamicSharedMemorySize,
                         SMEM_BYTES);

    k_norm<<<1024, 256>>>(anchor, pnegs);
    k_zero<<<1, 1>>>(out);
    k_gemm_lse<<<dim3(NT, MT), 256, SMEM_BYTES>>>();
    k_reduce<<<32, 128>>>(out);
}

// round 8
// speedup vs baseline: 2.2698x; 1.0387x over previous
#include <cuda_runtime.h>
#include <cuda_bf16.h>
#include <cuda_fp16.h>
#include <cuda_fp8.h>
#include <cstdint>

#define DEVINL __device__ __forceinline__

static constexpr int B = 4096;
static constexpr int D = 1024;
static constexpr int BM = 128;        // CTA M tile
static constexpr int BN = 128;        // CTA N tile
static constexpr int BK = 128;        // K chunk (128 fp8 = 128 B rows, SW128)
static constexpr int NT = B / BN;     // 32 N tiles
static constexpr int MT = B / BM;     // 32 M tiles
static constexpr int KC = D / BK;     // 8 K chunks
static constexpr int STAGES = 3;
static constexpr float FP8_SCALE = 32.0f;           // stored = 32 * x_hat
static constexpr float SCORE_MUL = 20.0f / (FP8_SCALE * FP8_SCALE);

static constexpr int A_SZ = BM * BK;            // 16384 bytes
static constexpr int B_SZ = BN * BK;            // 16384 bytes
static constexpr int STAGE_SZ = A_SZ + B_SZ;    // 32768
static constexpr int SMEM_BYTES = STAGES * STAGE_SZ + 1024;

// Scratch (allocation-free: __device__ globals)
__device__ uint8_t g_an[B * D];            // normalized anchors, e4m3 (x32)
__device__ uint8_t g_pn[B * D];            // normalized pos_negs, e4m3 (x32)
__device__ float2 g_part[NT * B];          // [ntile][row] (max, sumexp) - transposed
__device__ float g_diag[B];                // diag scores

DEVINL uint32_t smem_u32(const void* p) {
    uint32_t a;
    asm("{ .reg .u64 t; cvta.to.shared.u64 t, %1; cvt.u32.u64 %0, t; }"
        : "=r"(a) : "l"(p));
    return a;
}

DEVINL uint32_t swz128(uint32_t o) { return o ^ ((o >> 3) & 0x70); }

DEVINL void cp_async16(uint32_t dst, const void* src) {
    asm volatile("cp.async.cg.shared.global [%0], [%1], 16;"
                 :: "r"(dst), "l"(src) : "memory");
}

DEVINL void cp_commit() { asm volatile("cp.async.commit_group;" ::: "memory"); }

template <int N>
DEVINL void cp_wait() { asm volatile("cp.async.wait_group %0;" :: "n"(N) : "memory"); }

DEVINL void ldsm_x4(uint32_t addr, uint32_t& r0, uint32_t& r1, uint32_t& r2, uint32_t& r3) {
    asm volatile("ldmatrix.sync.aligned.m8n8.x4.shared.b16 {%0,%1,%2,%3}, [%4];"
                 : "=r"(r0), "=r"(r1), "=r"(r2), "=r"(r3) : "r"(addr));
}

// fp8 e4m3 MMA with f16 accumulator (2 D-regs instead of 4)
DEVINL void mma_fp8_h(uint32_t* c, const uint32_t* a, uint32_t b0, uint32_t b1) {
    asm volatile(
        "mma.sync.aligned.m16n8k32.row.col.f16.e4m3.e4m3.f16 "
        "{%0,%1}, {%2,%3,%4,%5}, {%6,%7}, {%0,%1};"
        : "+r"(c[0]), "+r"(c[1])
        : "r"(a[0]), "r"(a[1]), "r"(a[2]), "r"(a[3]), "r"(b0), "r"(b1));
}

// ============================================================
// Kernel 1: L2-normalize rows, write e4m3 (scaled by 32)
//           Also zeroes the output scalar (block 0, thread 0).
// ============================================================
__global__ void __launch_bounds__(256) k_norm(const float* __restrict__ a,
                                              const float* __restrict__ p,
                                              float* __restrict__ out) {
    if (blockIdx.x == 0 && threadIdx.x == 0) out[0] = 0.f;

    int w = threadIdx.x >> 5, lane = threadIdx.x & 31;
    int row = blockIdx.x * 8 + w;
    const float* src = (row < B) ? (a + (size_t)row * D) : (p + (size_t)(row - B) * D);
    uint8_t* dst = (row < B) ? (g_an + (size_t)row * D) : (g_pn + (size_t)(row - B) * D);

    // Phase 1: sum of squares (values not retained)
    float ss = 0.f;
#pragma unroll
    for (int r = 0; r < 8; ++r) {
        float4 v = reinterpret_cast<const float4*>(src)[r * 32 + lane];
        ss += v.x * v.x + v.y * v.y + v.z * v.z + v.w * v.w;
    }
#pragma unroll
    for (int o = 16; o > 0; o >>= 1) ss += __shfl_xor_sync(0xffffffffu, ss, o);

    float inv = FP8_SCALE / fmaxf(sqrtf(ss), 1e-8f);

    // Phase 2: reload (L2-resident) and emit fp8
#pragma unroll
    for (int r = 0; r < 8; ++r) {
        float4 v = reinterpret_cast<const float4*>(src)[r * 32 + lane];
        __nv_fp8x2_storage_t lo = __nv_cvt_float2_to_fp8x2(
            make_float2(v.x * inv, v.y * inv), __NV_SATFINITE, __NV_E4M3);
        __nv_fp8x2_storage_t hi = __nv_cvt_float2_to_fp8x2(
            make_float2(v.z * inv, v.w * inv), __NV_SATFINITE, __NV_E4M3);
        uint32_t pk = (uint32_t)lo | ((uint32_t)hi << 16);
        reinterpret_cast<uint32_t*>(dst)[r * 32 + lane] = pk;
    }
}

// ============================================================
// Kernel 2: e4m3 mma.sync f16-accum GEMM (128x128 tile, 32x64 warp)
//           + fused partial LSE
// ============================================================
__global__ void __launch_bounds__(256, 2) k_gemm_lse() {
    extern __shared__ char smem_raw[];
    uint32_t sb0 = smem_u32(smem_raw);
    uint32_t sb = (sb0 + 1023u) & ~1023u;
    char* base = smem_raw + (sb - sb0);

    const int tid = threadIdx.x;
    const int lane = tid & 31;
    const int w = tid >> 5;            // 0..7
    const int wm = w >> 1;             // 0..3  (M warp, 32 rows)
    const int wn = w & 1;              // 0..1  (N warp, 64 cols)
    const int bx = blockIdx.x;         // N tile
    const int by = blockIdx.y;         // M tile

    const uint8_t* Ag = g_an + (size_t)(by * BM) * D;
    const uint8_t* Bg = g_pn + (size_t)(bx * BN) * D;

    auto issue = [&](int kc, int s) {
        uint32_t sa = sb + s * STAGE_SZ;
        uint32_t sbB = sa + A_SZ;
#pragma unroll
        for (int i = 0; i < 4; ++i) {
            int idx = i * 256 + tid;        // 0..1023 (128 rows x 8 x 16B)
            int r = idx >> 3, c = idx & 7;
            cp_async16(sa + swz128((uint32_t)(r * 128 + c * 16)),
                       Ag + (size_t)r * D + kc * BK + c * 16);
        }
#pragma unroll
        for (int i = 0; i < 4; ++i) {
            int idx = i * 256 + tid;
            int r = idx >> 3, c = idx & 7;
            cp_async16(sbB + swz128((uint32_t)(r * 128 + c * 16)),
                       Bg + (size_t)r * D + kc * BK + c * 16);
        }
        cp_commit();
    };

    // f16x2 accumulators: [ri][nf][2]  (reg0 = rows g, reg1 = rows g+8)
    uint32_t acc[2][8][2];
#pragma unroll
    for (int ri = 0; ri < 2; ++ri)
#pragma unroll
        for (int nf = 0; nf < 8; ++nf) {
            acc[ri][nf][0] = 0u;
            acc[ri][nf][1] = 0u;
        }

    issue(0, 0);
    issue(1, 1);

    const int a_row_in = (lane & 7) + ((lane >> 3) & 1) * 8;  // 0..15
    const int a_kb_in  = (lane >> 4) * 16;                    // 0 or 16 bytes
    const int b_n_in   = (lane & 7) + ((lane >> 4) ? 8 : 0);  // 0..15
    const int b_kb_in  = ((lane >> 3) & 1) * 16;              // 0 or 16 bytes

    for (int kc = 0; kc < KC; ++kc) {
        cp_wait<STAGES - 2>();
        __syncthreads();
        if (kc + 2 < KC) issue(kc + 2, (kc + 2) % STAGES);

        uint32_t sA = sb + (kc % STAGES) * STAGE_SZ;
        uint32_t sB = sA + A_SZ;

#pragma unroll
        for (int s32 = 0; s32 < 4; ++s32) {
            int kb = s32 * 32;  // 32 bytes = k32 fp8 per step
            uint32_t a[2][4];
#pragma unroll
            for (int ri = 0; ri < 2; ++ri) {
                int row = wm * 32 + ri * 16 + a_row_in;
                ldsm_x4(sA + swz128((uint32_t)(row * 128 + kb + a_kb_in)),
                        a[ri][0], a[ri][1], a[ri][2], a[ri][3]);
            }
            uint32_t bf[4][4];
#pragma unroll
            for (int p = 0; p < 4; ++p) {
                int n = wn * 64 + p * 16 + b_n_in;
                ldsm_x4(sB + swz128((uint32_t)(n * 128 + kb + b_kb_in)),
                        bf[p][0], bf[p][1], bf[p][2], bf[p][3]);
            }
#pragma unroll
            for (int ri = 0; ri < 2; ++ri)
#pragma unroll
                for (int nf = 0; nf < 8; ++nf)
                    mma_fp8_h(acc[ri][nf], a[ri],
                              bf[nf >> 1][(nf & 1) * 2], bf[nf >> 1][(nf & 1) * 2 + 1]);
        }
        __syncthreads();
    }

    // ---- Epilogue: fused partial logsumexp + diag ----
    const int g = lane >> 2, tg = lane & 3;
    float2* hm = reinterpret_cast<float2*>(base);   // 128 rows x 2 halves

#pragma unroll
    for (int ri = 0; ri < 2; ++ri) {
#pragma unroll
        for (int h = 0; h < 2; ++h) {
            int rowl = wm * 32 + ri * 16 + h * 8 + g;
            int rowg = by * BM + rowl;
            float v[16];
            float mx = -1e30f;
#pragma unroll
            for (int nf = 0; nf < 8; ++nf) {
                float2 pr = __half22float2(
                    *reinterpret_cast<const __half2*>(&acc[ri][nf][h]));
#pragma unroll
                for (int c = 0; c < 2; ++c) {
                    float val = SCORE_MUL * ((c == 0) ? pr.x : pr.y);
                    v[nf * 2 + c] = val;
                    mx = fmaxf(mx, val);
                    int col = bx * BN + wn * 64 + nf * 8 + tg * 2 + c;
                    if (col == rowg) g_diag[rowg] = val;
                }
            }
            mx = fmaxf(mx, __shfl_xor_sync(0xffffffffu, mx, 1));
            mx = fmaxf(mx, __shfl_xor_sync(0xffffffffu, mx, 2));
            float sm = 0.f;
#pragma unroll
            for (int i = 0; i < 16; ++i) sm += __expf(v[i] - mx);
            sm += __shfl_xor_sync(0xffffffffu, sm, 1);
            sm += __shfl_xor_sync(0xffffffffu, sm, 2);
            if (tg == 0) hm[rowl * 2 + wn] = make_float2(mx, sm);
        }
    }
    __syncthreads();
    if (tid < 128) {
        float2 a0 = hm[tid * 2 + 0];
        float2 a1 = hm[tid * 2 + 1];
        float M = fmaxf(a0.x, a1.x);
        float S = a0.y * __expf(a0.x - M) + a1.y * __expf(a1.x - M);
        // transposed layout: coalesced write (consecutive tid -> consecutive row)
        g_part[(size_t)bx * B + by * BM + tid] = make_float2(M, S);
    }
}

// ============================================================
// Kernel 3: merge partials -> mean(logZ - diag)
//           64 CTAs x 256 threads; 4 threads/row x 8 partials each,
//           streamed online merge (low registers), shfl + smem reduce.
// ============================================================
__global__ void __launch_bounds__(256) k_reduce(float* __restrict__ out) {
    __shared__ float red[256];
    int tid = threadIdx.x;
    // 4 consecutive threads cover one row (8 ntile-partials each)
    int sub = tid & 3;                       // which quarter of NT
    int row = blockIdx.x * 64 + (tid >> 2);  // 64 rows per CTA

    float M = -1e30f, S = 0.f;
#pragma unroll
    for (int i = 0; i < NT / 4; ++i) {
        float2 q = g_part[(size_t)(sub * (NT / 4) + i) * B + row];
        if (q.x > M) {
            S = S * __expf(M - q.x) + q.y;
            M = q.x;
        } else {
            S += q.y * __expf(q.x - M);
        }
    }
    // merge across the 4-thread group (lanes sub=0..3)
#pragma unroll
    for (int o = 1; o < 4; o <<= 1) {
        float Mo = __shfl_xor_sync(0xffffffffu, M, o);
        float So = __shfl_xor_sync(0xffffffffu, S, o);
        float Mn = fmaxf(M, Mo);
        S = S * __expf(M - Mn) + So * __expf(Mo - Mn);
        M = Mn;
    }
    float acc = 0.f;
    if (sub == 0) acc = (M + logf(S)) - g_diag[row];

    red[tid] = acc;
    __syncthreads();
#pragma unroll
    for (int s = 128; s > 0; s >>= 1) {
        if (tid < s) red[tid] += red[tid + s];
        __syncthreads();
    }
    if (tid == 0) atomicAdd(out, red[0] * (1.0f / (float)B));
}

// ============================================================
extern "C" void kernel_launch(void* const* d_in, const int* in_sizes, int n_in,
                              void* d_out, int out_size) {
    const float* anchor = (const float*)d_in[0];
    const float* pnegs  = (const float*)d_in[1];
    float* out = (float*)d_out;

    cudaFuncSetAttribute(k_gemm_lse, cudaFuncAttributeMaxDynamicSharedMemorySize,
                         SMEM_BYTES);

    k_norm<<<1024, 256>>>(anchor, pnegs, out);
    k_gemm_lse<<<dim3(NT, MT), 256, SMEM_BYTES>>>();
    k_reduce<<<64, 256>>>(out);
}